// round 1
// baseline (speedup 1.0000x reference)
#include <cuda_runtime.h>

// Problem constants
#define NB 16
#define NC 3
#define H 768
#define W 768
#define HS 48            // H/16
#define WS 48            // W/16
#define NPIX (HS * WS)   // 2304
#define RADIUS 8

// Downsampled features: (f0, f1, f2, |f|^2) per (b, i). 16*2304*16B = 576 KB scratch.
__device__ float4 g_feats[NB * NPIX];

// ---------------------------------------------------------------------------
// Kernel 1: 16x bilinear downsample. Half-pixel centers => src = 16*i + 7.5,
// exact 0.5/0.5 weights => average of the 2x2 pixel block at (16y+7, 16x+7).
// ---------------------------------------------------------------------------
__global__ void resize_feats_kernel(const float* __restrict__ img) {
    int t = blockIdx.x * blockDim.x + threadIdx.x;
    if (t >= NB * NPIX) return;
    int b = t / NPIX;
    int i = t - b * NPIX;
    int yi = i / WS;
    int xi = i - yi * WS;
    int y0 = yi * 16 + 7;
    int x0 = xi * 16 + 7;

    float f[3];
#pragma unroll
    for (int c = 0; c < 3; ++c) {
        const float* p = img + ((size_t)(b * NC + c) * H + y0) * W + x0;
        // match separable resize: average rows first, then columns
        float r0 = 0.5f * (p[0] + p[1]);
        float r1 = 0.5f * (p[W] + p[W + 1]);
        f[c] = 0.5f * (r0 + r1);
    }
    float sq = f[0] * f[0] + f[1] * f[1] + f[2] * f[2];
    g_feats[t] = make_float4(f[0], f[1], f[2], sq);
}

// ---------------------------------------------------------------------------
// Kernel 2: affinity. One thread writes one float4 (4 consecutive j).
// Grid: x = row chunk (3 blocks x 192 thr x 4 = 2304 cols), y = i, z = b.
// Since 48 % 4 == 0, the 4 j's in a float4 share yj -> one dy test per thread.
// Combined exponent: exp(-cd/(2*0.1^2)) * exp(-sd/(2*5^2)) = exp(-(50*cd + 0.02*sd))
// ---------------------------------------------------------------------------
__global__ void __launch_bounds__(192) affinity_kernel(float4* __restrict__ out) {
    const int q  = blockIdx.x * 192 + threadIdx.x;   // float4 index within row, 0..575
    const int i  = blockIdx.y;                        // 0..2303
    const int b  = blockIdx.z;                        // 0..15

    const int j0 = q * 4;
    const int yj = j0 / WS;            // constant across the 4 lanes of this float4
    const int xj = j0 - yj * WS;
    const int yi = i / WS;
    const int xi = i - yi * WS;

    float4 v = make_float4(0.f, 0.f, 0.f, 0.f);

    const int dy = yi - yj;
    if (dy >= -RADIUS && dy <= RADIUS) {
        const float4* __restrict__ frow = g_feats + b * NPIX;
        const float4 fi = frow[i];
        const float sdy = (float)(dy * dy);
        float* vv = (float*)&v;
#pragma unroll
        for (int k = 0; k < 4; ++k) {
            const int dx = xi - (xj + k);
            if (dx >= -RADIUS && dx <= RADIUS) {
                const float4 fj = frow[j0 + k];
                float cd = fi.w + fj.w
                         - 2.0f * (fi.x * fj.x + fi.y * fj.y + fi.z * fj.z);
                cd = fmaxf(cd, 0.0f);
                const float e = -(50.0f * cd + 0.02f * (sdy + (float)(dx * dx)));
                vv[k] = __expf(e);
            }
        }
    }
    out[((size_t)b * NPIX + i) * (NPIX / 4) + q] = v;
}

// ---------------------------------------------------------------------------
extern "C" void kernel_launch(void* const* d_in, const int* in_sizes, int n_in,
                              void* d_out, int out_size) {
    const float* img = (const float*)d_in[0];
    float4* out = (float4*)d_out;

    const int nfeat = NB * NPIX;
    resize_feats_kernel<<<(nfeat + 255) / 256, 256>>>(img);

    dim3 grid(NPIX / 4 / 192, NPIX, NB);  // (3, 2304, 16)
    affinity_kernel<<<grid, 192>>>(out);
}